// round 1
// baseline (speedup 1.0000x reference)
#include <cuda_runtime.h>

// Problem shape (fixed)
namespace {
constexpr int B_  = 8;
constexpr int N_  = 1024;
constexpr int F_  = 1024;
constexpr int H_  = 8;
constexpr int HD_ = 128;

constexpr int BM = 128, BN = 128, BK = 8, TM = 8, TN = 8; // 256 threads
constexpr float SCALE_  = 0.08838834764831845f;  // 1/sqrt(128)
constexpr float NEGINF_ = -9e15f;
}

// Scratch (device globals: allocation-free rule)
__device__ float g_Q  [8u * 1024u * 1024u];        // [B,N,F]
__device__ float g_K  [8u * 1024u * 1024u];        // [B,N,F]
__device__ float g_Vp [8u * 1024u * 1024u];        // [B,N,F]  (v @ Wo folded)
__device__ float g_Wvp[1024u * 1024u];             // Wo_flat @ Wv
__device__ float g_bvp[1024u];
__device__ float g_A  [67108864ull];               // [B*H, N, N] = 256 MB

// ---------------------------------------------------------------------------
// bvp[o] = sum_f Wo_flat[o,f] * bv[f]
__global__ void fold_bias_kernel(const float* __restrict__ Wo,
                                 const float* __restrict__ bv) {
    const int o = blockIdx.x;
    float s = 0.f;
    for (int f = threadIdx.x; f < F_; f += 256)
        s += Wo[(size_t)o * F_ + f] * bv[f];
    __shared__ float red[8];
    #pragma unroll
    for (int off = 16; off; off >>= 1) s += __shfl_xor_sync(0xffffffffu, s, off);
    if ((threadIdx.x & 31) == 0) red[threadIdx.x >> 5] = s;
    __syncthreads();
    if (threadIdx.x == 0) {
        float t = 0.f;
        #pragma unroll
        for (int i = 0; i < 8; i++) t += red[i];
        g_bvp[o] = t;
    }
}

// ---------------------------------------------------------------------------
// One SGEMM, four modes:
//  MODE 0 (NT): C = A @ W^T + bias.  DST 0: g_Q<-obj@Wq^T, 1: g_K<-cross@Wk^T,
//               2: g_Vp<-cross@g_Wvp^T + g_bvp
//  MODE 1 (NN): g_Wvp = Wo_flat @ Wv
//  MODE 2 (NT): per (b,h): S = Qh @ Kh^T, epilogue scale+mask+labelbias -> g_A
//  MODE 3 (NN): per (b,h): out_h = A_{b,h} @ Vp_h + bo_h
template<int MODE, int DST = 0>
__global__ void __launch_bounds__(256, 2) sgemm_kernel(
    const float* __restrict__ Ag, const float* __restrict__ Bg,
    float* __restrict__ Cg, const float* __restrict__ biasg,
    const int* __restrict__ adjg, const float* __restrict__ labelg)
{
    constexpr bool TB = (MODE == 0 || MODE == 2);
    constexpr int  KD = (MODE == 2) ? HD_ : F_;

    __shared__ __align__(16) float As[BK][BM];
    __shared__ __align__(16) float Bs[BK][BN];

    const int tid  = threadIdx.x;
    const int tx   = tid & 15;
    const int ty   = tid >> 4;
    const int row0 = blockIdx.y * BM;
    const int col0 = blockIdx.x * BN;

    const float* A; const float* Bp; float* C;
    const float* biasp = nullptr;
    const int*   adjb  = nullptr;
    const float* labb  = nullptr;
    int lda, ldb, ldc;

    if constexpr (MODE == 0) {
        A = Ag; lda = F_; ldb = F_; ldc = F_;
        if constexpr (DST == 0)      { Bp = Bg;    C = g_Q;  biasp = biasg; }
        else if constexpr (DST == 1) { Bp = Bg;    C = g_K;  biasp = biasg; }
        else                         { Bp = g_Wvp; C = g_Vp; biasp = g_bvp; }
    } else if constexpr (MODE == 1) {
        A = Ag; Bp = Bg; C = g_Wvp; lda = F_; ldb = F_; ldc = F_;
    } else if constexpr (MODE == 2) {
        const int z = blockIdx.z, b = z >> 3, h = z & 7;
        A   = g_Q + (size_t)b * N_ * F_ + h * HD_;  lda = F_;
        Bp  = g_K + (size_t)b * N_ * F_ + h * HD_;  ldb = F_;
        C   = g_A + (size_t)z * N_ * N_;            ldc = N_;
        adjb = adjg  + (size_t)b * N_ * N_;
        labb = labelg + (size_t)b * N_ * N_;
    } else {
        const int z = blockIdx.z, b = z >> 3, h = z & 7;
        A   = g_A  + (size_t)z * N_ * N_;            lda = N_;
        Bp  = g_Vp + (size_t)b * N_ * F_ + h * HD_;  ldb = F_;
        C   = Cg   + (size_t)b * N_ * F_ + h * HD_;  ldc = F_;
        biasp = biasg + h * HD_;
    }

    float acc[TM][TN];
    #pragma unroll
    for (int i = 0; i < TM; i++)
        #pragma unroll
        for (int j = 0; j < TN; j++) acc[i][j] = 0.f;

    for (int k0 = 0; k0 < KD; k0 += BK) {
        {   // A tile: 128 rows x 8 k, k contiguous
            const int r  = tid >> 1;
            const int kc = (tid & 1) * 4;
            float4 v = *reinterpret_cast<const float4*>(
                A + (size_t)(row0 + r) * lda + k0 + kc);
            As[kc + 0][r] = v.x; As[kc + 1][r] = v.y;
            As[kc + 2][r] = v.z; As[kc + 3][r] = v.w;
        }
        if constexpr (TB) {  // B rows indexed by output column, k contiguous
            const int r  = tid >> 1;
            const int kc = (tid & 1) * 4;
            float4 v = *reinterpret_cast<const float4*>(
                Bp + (size_t)(col0 + r) * ldb + k0 + kc);
            Bs[kc + 0][r] = v.x; Bs[kc + 1][r] = v.y;
            Bs[kc + 2][r] = v.z; Bs[kc + 3][r] = v.w;
        } else {             // B rows indexed by k, n contiguous
            const int kr = tid >> 5;
            const int nc = (tid & 31) * 4;
            float4 v = *reinterpret_cast<const float4*>(
                Bp + (size_t)(k0 + kr) * ldb + col0 + nc);
            *reinterpret_cast<float4*>(&Bs[kr][nc]) = v;
        }
        __syncthreads();

        #pragma unroll
        for (int kk = 0; kk < BK; kk++) {
            float a[TM], bb[TN];
            #pragma unroll
            for (int i = 0; i < TM; i += 4)
                *reinterpret_cast<float4*>(&a[i]) =
                    *reinterpret_cast<const float4*>(&As[kk][ty * TM + i]);
            #pragma unroll
            for (int j = 0; j < TN; j += 4)
                *reinterpret_cast<float4*>(&bb[j]) =
                    *reinterpret_cast<const float4*>(&Bs[kk][tx * TN + j]);
            #pragma unroll
            for (int i = 0; i < TM; i++)
                #pragma unroll
                for (int j = 0; j < TN; j++)
                    acc[i][j] = fmaf(a[i], bb[j], acc[i][j]);
        }
        __syncthreads();
    }

    #pragma unroll
    for (int i = 0; i < TM; i++) {
        const int r = row0 + ty * TM + i;
        float* crow = C + (size_t)r * ldc;
        #pragma unroll
        for (int j = 0; j < TN; j += 4) {
            const int c = col0 + tx * TN + j;
            float4 o = make_float4(acc[i][j], acc[i][j+1], acc[i][j+2], acc[i][j+3]);
            if constexpr (MODE == 0 || MODE == 3) {
                float4 bb = *reinterpret_cast<const float4*>(biasp + c);
                o.x += bb.x; o.y += bb.y; o.z += bb.z; o.w += bb.w;
            }
            if constexpr (MODE == 2) {
                int4   av = *reinterpret_cast<const int4*>(adjb + (size_t)r * N_ + c);
                float4 lv = *reinterpret_cast<const float4*>(labb + (size_t)r * N_ + c);
                o.x = (av.x > 0 ? o.x * SCALE_ : NEGINF_) + lv.x;
                o.y = (av.y > 0 ? o.y * SCALE_ : NEGINF_) + lv.y;
                o.z = (av.z > 0 ? o.z * SCALE_ : NEGINF_) + lv.z;
                o.w = (av.w > 0 ? o.w * SCALE_ : NEGINF_) + lv.w;
            }
            *reinterpret_cast<float4*>(crow + c) = o;
        }
    }
}

// ---------------------------------------------------------------------------
// Row softmax over g_A (one block per row of 1024)
__global__ void softmax_kernel() {
    const size_t row = blockIdx.x;
    float* p = g_A + row * (size_t)N_;
    const int t = threadIdx.x;
    float4 v = reinterpret_cast<float4*>(p)[t];

    __shared__ float sm[8], ss[8];
    float mx = fmaxf(fmaxf(v.x, v.y), fmaxf(v.z, v.w));
    #pragma unroll
    for (int o = 16; o; o >>= 1) mx = fmaxf(mx, __shfl_xor_sync(0xffffffffu, mx, o));
    if ((t & 31) == 0) sm[t >> 5] = mx;
    __syncthreads();
    mx = sm[0];
    #pragma unroll
    for (int w = 1; w < 8; w++) mx = fmaxf(mx, sm[w]);

    float4 e;
    e.x = __expf(v.x - mx); e.y = __expf(v.y - mx);
    e.z = __expf(v.z - mx); e.w = __expf(v.w - mx);
    float s = e.x + e.y + e.z + e.w;
    #pragma unroll
    for (int o = 16; o; o >>= 1) s += __shfl_xor_sync(0xffffffffu, s, o);
    if ((t & 31) == 0) ss[t >> 5] = s;
    __syncthreads();
    s = ss[0];
    #pragma unroll
    for (int w = 1; w < 8; w++) s += ss[w];

    const float inv = 1.0f / s;
    e.x *= inv; e.y *= inv; e.z *= inv; e.w *= inv;
    reinterpret_cast<float4*>(p)[t] = e;
}

// ---------------------------------------------------------------------------
// att_avg[b,n,m] = (1/H) * sum_h A[b,h,n,m]
__global__ void attavg_kernel(float* __restrict__ out2) {
    const int i4 = blockIdx.x * 256 + threadIdx.x;  // over B*N*N/4 float4s
    const int b  = i4 >> 18;                        // / (N*N/4)
    const size_t off = (size_t)(i4 & 262143) * 4;
    const float* base = g_A + (size_t)b * H_ * N_ * N_ + off;
    float4 s = make_float4(0.f, 0.f, 0.f, 0.f);
    #pragma unroll
    for (int h = 0; h < H_; h++) {
        float4 v = *reinterpret_cast<const float4*>(base + (size_t)h * N_ * N_);
        s.x += v.x; s.y += v.y; s.z += v.z; s.w += v.w;
    }
    s.x *= 0.125f; s.y *= 0.125f; s.z *= 0.125f; s.w *= 0.125f;
    *reinterpret_cast<float4*>(out2 + (size_t)b * N_ * N_ + off) = s;
}

// ---------------------------------------------------------------------------
extern "C" void kernel_launch(void* const* d_in, const int* in_sizes, int n_in,
                              void* d_out, int out_size) {
    const float* obj   = (const float*)d_in[0];
    const float* cross = (const float*)d_in[1];
    const int*   adj   = (const int*)  d_in[2];
    const float* label = (const float*)d_in[3];
    const float* Wq    = (const float*)d_in[4];
    const float* bq    = (const float*)d_in[5];
    const float* Wk    = (const float*)d_in[6];
    const float* bk    = (const float*)d_in[7];
    const float* Wv    = (const float*)d_in[8];
    const float* bv    = (const float*)d_in[9];
    const float* Wo    = (const float*)d_in[10];
    const float* bo    = (const float*)d_in[11];

    float* out     = (float*)d_out;
    float* out_att = out + (size_t)B_ * N_ * F_;   // second tuple element

    // weight folding: Wvp = Wo_flat @ Wv, bvp = Wo_flat @ bv
    fold_bias_kernel<<<F_, 256>>>(Wo, bv);
    sgemm_kernel<1, 0><<<dim3(8, 8), 256>>>(Wo, Wv, nullptr, nullptr, nullptr, nullptr);

    // projections
    sgemm_kernel<0, 0><<<dim3(8, 64), 256>>>(obj,   Wq, nullptr, bq, nullptr, nullptr);
    sgemm_kernel<0, 1><<<dim3(8, 64), 256>>>(cross, Wk, nullptr, bk, nullptr, nullptr);
    sgemm_kernel<0, 2><<<dim3(8, 64), 256>>>(cross, nullptr, nullptr, nullptr, nullptr, nullptr);

    // scores (masked, biased) -> softmax -> outputs
    sgemm_kernel<2, 0><<<dim3(8, 8, 64), 256>>>(nullptr, nullptr, nullptr, nullptr, adj, label);
    softmax_kernel<<<B_ * H_ * N_, 256>>>();
    sgemm_kernel<3, 0><<<dim3(1, 8, 64), 256>>>(nullptr, nullptr, out, bo, nullptr, nullptr);
    attavg_kernel<<<8192, 256>>>(out_att);
}

// round 3
// speedup vs baseline: 2.6606x; 2.6606x over previous
#include <cuda_runtime.h>
#include <cstdint>

namespace {
constexpr int B_  = 8;
constexpr int N_  = 1024;
constexpr int F_  = 1024;
constexpr int H_  = 8;
constexpr int HD_ = 128;
constexpr float SCALE_  = 0.08838834764831845f;  // 1/sqrt(128)
constexpr float NEGINF_ = -9e15f;

constexpr int BM = 128, BN = 128, BK = 16;
constexpr int PAD = 20;                 // smem row stride (floats): conflict-free frags
constexpr int STG = BM * PAD;           // 2560 floats per tile-stage
}

// ------------------------- scratch (device globals) -------------------------
__device__ float g_objR  [8u * 1024u * 1024u];
__device__ float g_crossR[8u * 1024u * 1024u];
__device__ float g_WqR[1024u * 1024u];
__device__ float g_WkR[1024u * 1024u];
__device__ float g_WoR[1024u * 1024u];
__device__ float g_WvT[1024u * 1024u];        // Wv transposed+rounded: [j][f]
__device__ float g_Wvp[1024u * 1024u];        // Wo_flat @ Wv (rounded)
__device__ float g_bvp[1024u];
__device__ float g_Q  [8u * 1024u * 1024u];   // [B,N,F] rounded
__device__ float g_K  [8u * 1024u * 1024u];   // [B,N,F] rounded
__device__ float g_VpT[8u * 1024u * 1024u];   // [F][B*N] rounded (transposed Vp)
__device__ float g_A  [67108864ull];          // [B*H,N,N]

// ------------------------------- helpers ------------------------------------
__device__ __forceinline__ float rna(float x) {
    uint32_t u;
    asm("cvt.rna.tf32.f32 %0, %1;" : "=r"(u) : "f"(x));
    return __uint_as_float(u);
}

__device__ __forceinline__ void cp16(float* s, const float* g) {
    uint32_t sa = (uint32_t)__cvta_generic_to_shared(s);
    asm volatile("cp.async.cg.shared.global [%0], [%1], 16;\n" :: "r"(sa), "l"(g));
}

__device__ __forceinline__ void mma_tf32(float* d, const uint32_t* a, const uint32_t* b) {
    asm volatile(
        "mma.sync.aligned.m16n8k8.row.col.f32.tf32.tf32.f32 "
        "{%0,%1,%2,%3},{%4,%5,%6,%7},{%8,%9},{%0,%1,%2,%3};\n"
        : "+f"(d[0]), "+f"(d[1]), "+f"(d[2]), "+f"(d[3])
        : "r"(a[0]), "r"(a[1]), "r"(a[2]), "r"(a[3]), "r"(b[0]), "r"(b[1]));
}

// --------------------------- pre/post passes --------------------------------
__global__ void round_pass(const float* __restrict__ in, float* __restrict__ out) {
    size_t i = (size_t)(blockIdx.x * 256 + threadIdx.x) * 4;
    float4 v = *(const float4*)(in + i);
    v.x = rna(v.x); v.y = rna(v.y); v.z = rna(v.z); v.w = rna(v.w);
    *(float4*)(out + i) = v;
}

// g_WvT[j][f] = rna(Wv[f][j])
__global__ void transpose_round_kernel(const float* __restrict__ in, float* __restrict__ out) {
    __shared__ float t[32][33];
    const int bx = blockIdx.x * 32, by = blockIdx.y * 32;
    const int x = threadIdx.x, y0 = threadIdx.y;
    #pragma unroll
    for (int yy = 0; yy < 32; yy += 8)
        t[y0 + yy][x] = in[(size_t)(by + y0 + yy) * 1024 + bx + x];
    __syncthreads();
    #pragma unroll
    for (int yy = 0; yy < 32; yy += 8)
        out[(size_t)(bx + y0 + yy) * 1024 + by + x] = rna(t[x][y0 + yy]);
}

// bvp[o] = sum_f Wo_flat[o,f] * bv[f]   (exact fp32)
__global__ void fold_bias_kernel(const float* __restrict__ Wo, const float* __restrict__ bv) {
    const int o = blockIdx.x;
    float s = 0.f;
    for (int f = threadIdx.x; f < F_; f += 256)
        s += Wo[(size_t)o * F_ + f] * bv[f];
    __shared__ float red[8];
    #pragma unroll
    for (int off = 16; off; off >>= 1) s += __shfl_xor_sync(0xffffffffu, s, off);
    if ((threadIdx.x & 31) == 0) red[threadIdx.x >> 5] = s;
    __syncthreads();
    if (threadIdx.x == 0) {
        float t = 0.f;
        #pragma unroll
        for (int i = 0; i < 8; i++) t += red[i];
        g_bvp[o] = t;
    }
}

// ---------------------- TF32 tensor-core NT GEMM ----------------------------
// MODE 0: fold      g_Wvp = g_WoR @ g_WvT^T                (round)
// MODE 1: Q         g_Q   = g_objR @ g_WqR^T + bq          (round)
// MODE 2: K         g_K   = g_crossR @ g_WkR^T + bk        (round)
// MODE 3: Vp        g_VpT = (g_crossR @ g_Wvp^T + bvp)^T   (round, transposed store)
// MODE 4: scores    g_A[z] = Qh @ Kh^T  (K=128), epi scale/mask/label
// MODE 5: AV        out_h = A_z @ VpT_h^T + bo_h
template<int MODE>
__global__ void __launch_bounds__(128, 2) tgemm(
    const float* __restrict__ bias, const int* __restrict__ adj,
    const float* __restrict__ label, float* __restrict__ outp)
{
    __shared__ __align__(16) float sm[4 * STG];   // 40KB

    const int tid  = threadIdx.x;
    const int warp = tid >> 5, lane = tid & 31;
    const int wm0 = (warp & 1) * 64, wn0 = (warp >> 1) * 64;
    const int r = lane >> 2, c = lane & 3;
    const int ro = blockIdx.y * BM, co = blockIdx.x * BN;

    int zb = 0, zh = 0;
    if constexpr (MODE >= 4) { const int z = blockIdx.z; zb = z >> 3; zh = z & 7; }

    const float* Ap; const float* Bp; float* Cp = nullptr;
    int lda, ldb, ldc, KD;
    if constexpr (MODE == 0) { Ap = g_WoR;   Bp = g_WvT; Cp = g_Wvp; lda = ldb = ldc = F_; KD = F_; }
    if constexpr (MODE == 1) { Ap = g_objR;  Bp = g_WqR; Cp = g_Q;   lda = ldb = ldc = F_; KD = F_; }
    if constexpr (MODE == 2) { Ap = g_crossR;Bp = g_WkR; Cp = g_K;   lda = ldb = ldc = F_; KD = F_; }
    if constexpr (MODE == 3) { Ap = g_crossR;Bp = g_Wvp; Cp = g_VpT; lda = ldb = F_; ldc = 8192; KD = F_; }
    if constexpr (MODE == 4) {
        Ap = g_Q + (size_t)zb * N_ * F_ + zh * HD_; lda = F_;
        Bp = g_K + (size_t)zb * N_ * F_ + zh * HD_; ldb = F_;
        Cp = g_A + (size_t)(blockIdx.z) * N_ * N_;  ldc = N_; KD = HD_;
    }
    if constexpr (MODE == 5) {
        Ap = g_A + (size_t)(blockIdx.z) * N_ * N_;          lda = N_;
        Bp = g_VpT + (size_t)zh * HD_ * 8192 + zb * N_;     ldb = 8192;
        Cp = outp + (size_t)zb * N_ * F_ + zh * HD_;        ldc = F_; KD = F_;
    }

    float acc[4][8][4];
    #pragma unroll
    for (int i = 0; i < 4; i++)
        #pragma unroll
        for (int j = 0; j < 8; j++)
            #pragma unroll
            for (int k = 0; k < 4; k++) acc[i][j][k] = 0.f;

    auto loadTile = [&](int kt, int s) {
        const int k0 = kt * BK;
        #pragma unroll
        for (int i = 0; i < 4; i++) {
            const int q = tid + 128 * i, row = q >> 2, k4 = q & 3;
            cp16(&sm[s * STG + row * PAD + k4 * 4],
                 Ap + (size_t)(ro + row) * lda + k0 + k4 * 4);
        }
        #pragma unroll
        for (int i = 0; i < 4; i++) {
            const int q = tid + 128 * i, row = q >> 2, k4 = q & 3;
            cp16(&sm[2 * STG + s * STG + row * PAD + k4 * 4],
                 Bp + (size_t)(co + row) * ldb + k0 + k4 * 4);
        }
    };

    const int T = KD / BK;
    loadTile(0, 0);
    asm volatile("cp.async.commit_group;\n");

    for (int kt = 0; kt < T; ++kt) {
        const int s = kt & 1;
        if (kt + 1 < T) {
            loadTile(kt + 1, s ^ 1);
            asm volatile("cp.async.commit_group;\n");
            asm volatile("cp.async.wait_group 1;\n");
        } else {
            asm volatile("cp.async.wait_group 0;\n");
        }
        __syncthreads();

        const float* As = &sm[s * STG];
        const float* Bs = &sm[2 * STG + s * STG];
        #pragma unroll
        for (int kk = 0; kk < 2; ++kk) {
            const int kb = kk * 8;
            uint32_t a[4][4], b[8][2];
            #pragma unroll
            for (int mt = 0; mt < 4; mt++) {
                const int rb = wm0 + mt * 16;
                a[mt][0] = __float_as_uint(As[(rb + r    ) * PAD + kb + c    ]);
                a[mt][1] = __float_as_uint(As[(rb + r + 8) * PAD + kb + c    ]);
                a[mt][2] = __float_as_uint(As[(rb + r    ) * PAD + kb + c + 4]);
                a[mt][3] = __float_as_uint(As[(rb + r + 8) * PAD + kb + c + 4]);
            }
            #pragma unroll
            for (int nt = 0; nt < 8; nt++) {
                const int nb = wn0 + nt * 8 + r;
                b[nt][0] = __float_as_uint(Bs[nb * PAD + kb + c    ]);
                b[nt][1] = __float_as_uint(Bs[nb * PAD + kb + c + 4]);
            }
            #pragma unroll
            for (int mt = 0; mt < 4; mt++)
                #pragma unroll
                for (int nt = 0; nt < 8; nt++) mma_tf32(acc[mt][nt], a[mt], b[nt]);
        }
        __syncthreads();
    }

    // ------------------------------ epilogues -------------------------------
    if constexpr (MODE == 3) {
        #pragma unroll
        for (int half = 0; half < 2; ++half) {
            __syncthreads();
            #pragma unroll
            for (int mt = 0; mt < 4; mt++)
                #pragma unroll
                for (int nt = 0; nt < 8; nt++)
                    #pragma unroll
                    for (int h2 = 0; h2 < 2; h2++)
                        #pragma unroll
                        for (int j = 0; j < 2; j++) {
                            const int colL = wn0 + nt * 8 + c * 2 + j;
                            if ((colL >> 6) == half) {
                                const int rowL = wm0 + mt * 16 + r + h2 * 8;
                                sm[(colL & 63) * 132 + rowL] =
                                    rna(acc[mt][nt][h2 * 2 + j] + g_bvp[co + colL]);
                            }
                        }
            __syncthreads();
            #pragma unroll
            for (int i = 0; i < 16; i++) {
                const int q = tid + 128 * i;            // 0..2047
                const int fr = q >> 5, m4 = q & 31;
                float4 v = *(const float4*)&sm[fr * 132 + m4 * 4];
                *(float4*)&g_VpT[(size_t)(co + half * 64 + fr) * 8192 + ro + m4 * 4] = v;
            }
        }
        return;
    }

    const int* adjr = nullptr; const float* labr = nullptr;
    if constexpr (MODE == 4) {
        adjr = adj   + (size_t)zb * N_ * N_;
        labr = label + (size_t)zb * N_ * N_;
    }

    #pragma unroll
    for (int mt = 0; mt < 4; mt++)
        #pragma unroll
        for (int nt = 0; nt < 8; nt++)
            #pragma unroll
            for (int h2 = 0; h2 < 2; h2++) {
                const int row  = ro + wm0 + mt * 16 + r + h2 * 8;
                const int colL = wn0 + nt * 8 + c * 2;
                const int col  = co + colL;
                float v0 = acc[mt][nt][h2 * 2 + 0];
                float v1 = acc[mt][nt][h2 * 2 + 1];
                if constexpr (MODE == 0) { v0 = rna(v0); v1 = rna(v1); }
                if constexpr (MODE == 1 || MODE == 2) {
                    v0 = rna(v0 + bias[col]); v1 = rna(v1 + bias[col + 1]);
                }
                if constexpr (MODE == 4) {
                    const int2   av = *(const int2*)  &adjr[(size_t)row * N_ + col];
                    const float2 lv = *(const float2*)&labr[(size_t)row * N_ + col];
                    v0 = (av.x > 0 ? v0 * SCALE_ : NEGINF_) + lv.x;
                    v1 = (av.y > 0 ? v1 * SCALE_ : NEGINF_) + lv.y;
                }
                if constexpr (MODE == 5) {
                    v0 += bias[colL]; v1 += bias[colL + 1];   // bias = bo + h*HD
                }
                *(float2*)&Cp[(size_t)row * ldc + col] = make_float2(v0, v1);
            }
}

// --------------------------- softmax (rounds output) ------------------------
__global__ void softmax_kernel() {
    const size_t row = blockIdx.x;
    float* p = g_A + row * (size_t)N_;
    const int t = threadIdx.x;
    float4 v = reinterpret_cast<float4*>(p)[t];

    __shared__ float smx[8], ssm[8];
    float mx = fmaxf(fmaxf(v.x, v.y), fmaxf(v.z, v.w));
    #pragma unroll
    for (int o = 16; o; o >>= 1) mx = fmaxf(mx, __shfl_xor_sync(0xffffffffu, mx, o));
    if ((t & 31) == 0) smx[t >> 5] = mx;
    __syncthreads();
    mx = smx[0];
    #pragma unroll
    for (int w = 1; w < 8; w++) mx = fmaxf(mx, smx[w]);

    float4 e;
    e.x = __expf(v.x - mx); e.y = __expf(v.y - mx);
    e.z = __expf(v.z - mx); e.w = __expf(v.w - mx);
    float s = e.x + e.y + e.z + e.w;
    #pragma unroll
    for (int o = 16; o; o >>= 1) s += __shfl_xor_sync(0xffffffffu, s, o);
    if ((t & 31) == 0) ssm[t >> 5] = s;
    __syncthreads();
    s = ssm[0];
    #pragma unroll
    for (int w = 1; w < 8; w++) s += ssm[w];

    const float inv = 1.0f / s;
    e.x = rna(e.x * inv); e.y = rna(e.y * inv);
    e.z = rna(e.z * inv); e.w = rna(e.w * inv);
    reinterpret_cast<float4*>(p)[t] = e;
}

// att_avg[b,n,m] = (1/H) * sum_h A[b,h,n,m]
__global__ void attavg_kernel(float* __restrict__ out2) {
    const int i4 = blockIdx.x * 256 + threadIdx.x;
    const int b  = i4 >> 18;
    const size_t off = (size_t)(i4 & 262143) * 4;
    const float* base = g_A + (size_t)b * H_ * N_ * N_ + off;
    float4 s = make_float4(0.f, 0.f, 0.f, 0.f);
    #pragma unroll
    for (int h = 0; h < H_; h++) {
        float4 v = *(const float4*)(base + (size_t)h * N_ * N_);
        s.x += v.x; s.y += v.y; s.z += v.z; s.w += v.w;
    }
    s.x *= 0.125f; s.y *= 0.125f; s.z *= 0.125f; s.w *= 0.125f;
    *(float4*)(out2 + (size_t)b * N_ * N_ + off) = s;
}

// ----------------------------------------------------------------------------
extern "C" void kernel_launch(void* const* d_in, const int* in_sizes, int n_in,
                              void* d_out, int out_size) {
    const float* obj   = (const float*)d_in[0];
    const float* cross = (const float*)d_in[1];
    const int*   adj   = (const int*)  d_in[2];
    const float* label = (const float*)d_in[3];
    const float* Wq    = (const float*)d_in[4];
    const float* bq    = (const float*)d_in[5];
    const float* Wk    = (const float*)d_in[6];
    const float* bk    = (const float*)d_in[7];
    const float* Wv    = (const float*)d_in[8];
    const float* bv    = (const float*)d_in[9];
    const float* Wo    = (const float*)d_in[10];
    const float* bo    = (const float*)d_in[11];

    float* out     = (float*)d_out;
    float* out_att = out + (size_t)B_ * N_ * F_;

    float *objR, *crossR, *WqR, *WkR, *WoR, *WvT;
    cudaGetSymbolAddress((void**)&objR,   g_objR);
    cudaGetSymbolAddress((void**)&crossR, g_crossR);
    cudaGetSymbolAddress((void**)&WqR,    g_WqR);
    cudaGetSymbolAddress((void**)&WkR,    g_WkR);
    cudaGetSymbolAddress((void**)&WoR,    g_WoR);
    cudaGetSymbolAddress((void**)&WvT,    g_WvT);

    // round external GEMM inputs to tf32 (RNA)
    round_pass<<<8192, 256>>>(obj,   objR);
    round_pass<<<8192, 256>>>(cross, crossR);
    round_pass<<<1024, 256>>>(Wq, WqR);
    round_pass<<<1024, 256>>>(Wk, WkR);
    round_pass<<<1024, 256>>>(Wo, WoR);
    transpose_round_kernel<<<dim3(32, 32), dim3(32, 8)>>>(Wv, WvT);
    fold_bias_kernel<<<F_, 256>>>(Wo, bv);

    // GEMMs
    tgemm<0><<<dim3(8, 8),     128>>>(nullptr, nullptr, nullptr, nullptr);  // fold
    tgemm<1><<<dim3(8, 64),    128>>>(bq,      nullptr, nullptr, nullptr);  // Q
    tgemm<2><<<dim3(8, 64),    128>>>(bk,      nullptr, nullptr, nullptr);  // K
    tgemm<3><<<dim3(8, 64),    128>>>(nullptr, nullptr, nullptr, nullptr);  // VpT
    tgemm<4><<<dim3(8, 8, 64), 128>>>(nullptr, adj,     label,   nullptr);  // scores
    softmax_kernel<<<B_ * H_ * N_, 256>>>();
    tgemm<5><<<dim3(1, 8, 64), 128>>>(bo,      nullptr, nullptr, out);      // AV
    attavg_kernel<<<8192, 256>>>(out_att);
}

// round 4
// speedup vs baseline: 3.7026x; 1.3917x over previous
#include <cuda_runtime.h>
#include <cstdint>

namespace {
constexpr int B_  = 8;
constexpr int N_  = 1024;
constexpr int F_  = 1024;
constexpr int H_  = 8;
constexpr int HD_ = 128;
constexpr float SCALE_  = 0.08838834764831845f;  // 1/sqrt(128)
constexpr float NEGINF_ = -9e15f;

constexpr int BM = 128, BN = 128, BK = 32;
// dynamic smem: A[2][128][32] + B[2][128][32] floats = 64 KB
constexpr int STAGE_BYTES = BM * BK * 4;         // 16384
constexpr int SMEM_BYTES  = 4 * STAGE_BYTES;     // 65536
}

// ------------------------- scratch (device globals) -------------------------
__device__ float g_objR  [8u * 1024u * 1024u];
__device__ float g_crossR[8u * 1024u * 1024u];
__device__ float g_WqR[1024u * 1024u];
__device__ float g_WkR[1024u * 1024u];
__device__ float g_WoR[1024u * 1024u];
__device__ float g_WvT[1024u * 1024u];        // Wv transposed+rounded: [j][f]
__device__ float g_Wvp[1024u * 1024u];        // Wo_flat @ Wv (rounded)
__device__ float g_bvp[1024u];
__device__ float g_Q  [8u * 1024u * 1024u];   // [B,N,F] rounded
__device__ float g_K  [8u * 1024u * 1024u];   // [B,N,F] rounded
__device__ float g_VpT[8u * 1024u * 1024u];   // [F][B*N] rounded (transposed Vp)
__device__ float g_A  [67108864ull];          // [B*H,N,N]

// ------------------------------- helpers ------------------------------------
__device__ __forceinline__ float rna(float x) {
    uint32_t u;
    asm("cvt.rna.tf32.f32 %0, %1;" : "=r"(u) : "f"(x));
    return __uint_as_float(u);
}

__device__ __forceinline__ void cp16s(uint32_t saddr, const float* g) {
    asm volatile("cp.async.cg.shared.global [%0], [%1], 16;\n" :: "r"(saddr), "l"(g));
}

__device__ __forceinline__ void ldsm4(uint32_t& r0, uint32_t& r1, uint32_t& r2,
                                      uint32_t& r3, uint32_t saddr) {
    asm volatile("ldmatrix.sync.aligned.m8n8.x4.shared.b16 {%0,%1,%2,%3}, [%4];"
                 : "=r"(r0), "=r"(r1), "=r"(r2), "=r"(r3) : "r"(saddr));
}

__device__ __forceinline__ void mma_tf32(float* d, const uint32_t* a, const uint32_t* b) {
    asm volatile(
        "mma.sync.aligned.m16n8k8.row.col.f32.tf32.tf32.f32 "
        "{%0,%1,%2,%3},{%4,%5,%6,%7},{%8,%9},{%0,%1,%2,%3};\n"
        : "+f"(d[0]), "+f"(d[1]), "+f"(d[2]), "+f"(d[3])
        : "r"(a[0]), "r"(a[1]), "r"(a[2]), "r"(a[3]), "r"(b[0]), "r"(b[1]));
}

// --------------------------- pre/post passes --------------------------------
__global__ void round_pass(const float* __restrict__ in, float* __restrict__ out) {
    size_t i = (size_t)(blockIdx.x * 256 + threadIdx.x) * 4;
    float4 v = *(const float4*)(in + i);
    v.x = rna(v.x); v.y = rna(v.y); v.z = rna(v.z); v.w = rna(v.w);
    *(float4*)(out + i) = v;
}

// g_WvT[j][f] = rna(Wv[f][j])
__global__ void transpose_round_kernel(const float* __restrict__ in, float* __restrict__ out) {
    __shared__ float t[32][33];
    const int bx = blockIdx.x * 32, by = blockIdx.y * 32;
    const int x = threadIdx.x, y0 = threadIdx.y;
    #pragma unroll
    for (int yy = 0; yy < 32; yy += 8)
        t[y0 + yy][x] = in[(size_t)(by + y0 + yy) * 1024 + bx + x];
    __syncthreads();
    #pragma unroll
    for (int yy = 0; yy < 32; yy += 8)
        out[(size_t)(bx + y0 + yy) * 1024 + by + x] = rna(t[x][y0 + yy]);
}

// bvp[o] = sum_f Wo_flat[o,f] * bv[f]   (exact fp32)
__global__ void fold_bias_kernel(const float* __restrict__ Wo, const float* __restrict__ bv) {
    const int o = blockIdx.x;
    float s = 0.f;
    for (int f = threadIdx.x; f < F_; f += 256)
        s += Wo[(size_t)o * F_ + f] * bv[f];
    __shared__ float red[8];
    #pragma unroll
    for (int off = 16; off; off >>= 1) s += __shfl_xor_sync(0xffffffffu, s, off);
    if ((threadIdx.x & 31) == 0) red[threadIdx.x >> 5] = s;
    __syncthreads();
    if (threadIdx.x == 0) {
        float t = 0.f;
        #pragma unroll
        for (int i = 0; i < 8; i++) t += red[i];
        g_bvp[o] = t;
    }
}

// ---------------------- TF32 tensor-core NT GEMM ----------------------------
// Swizzled smem tiles: 128 rows x 128B (BK=32 floats); element (row, k) lives at
// byte  row*128 + (((k>>2) ^ (row&7)) << 4) + (k&3)*4.
// Fragments come out of smem with single ldmatrix.x4 ops.
//
// MODE 0: fold      g_Wvp = g_WoR @ g_WvT^T                (round)
// MODE 1: Q         g_Q   = g_objR @ g_WqR^T + bq          (round)
// MODE 2: K         g_K   = g_crossR @ g_WkR^T + bk        (round)
// MODE 3: Vp        g_VpT = (g_crossR @ g_Wvp^T + bvp)^T   (round, transposed store)
// MODE 4: scores    g_A[z] = Qh @ Kh^T  (K=128), epi scale/mask/label
// MODE 5: AV        out_h = A_z @ VpT_h^T + bo_h
template<int MODE>
__global__ void __launch_bounds__(128, 2) tgemm(
    const float* __restrict__ bias, const int* __restrict__ adj,
    const float* __restrict__ label, float* __restrict__ outp)
{
    extern __shared__ __align__(16) float smf[];
    const uint32_t smemU = (uint32_t)__cvta_generic_to_shared(smf);

    const int tid  = threadIdx.x;
    const int warp = tid >> 5, lane = tid & 31;
    const int wm0 = (warp & 1) * 64, wn0 = (warp >> 1) * 64;
    const int r = lane >> 2, c = lane & 3;
    const int ro = blockIdx.y * BM, co = blockIdx.x * BN;

    int zb = 0, zh = 0;
    if constexpr (MODE >= 4) { const int z = blockIdx.z; zb = z >> 3; zh = z & 7; }

    const float* Ap; const float* Bp; float* Cp = nullptr;
    int lda, ldb, ldc, KD;
    if constexpr (MODE == 0) { Ap = g_WoR;   Bp = g_WvT; Cp = g_Wvp; lda = ldb = ldc = F_; KD = F_; }
    if constexpr (MODE == 1) { Ap = g_objR;  Bp = g_WqR; Cp = g_Q;   lda = ldb = ldc = F_; KD = F_; }
    if constexpr (MODE == 2) { Ap = g_crossR;Bp = g_WkR; Cp = g_K;   lda = ldb = ldc = F_; KD = F_; }
    if constexpr (MODE == 3) { Ap = g_crossR;Bp = g_Wvp; Cp = g_VpT; lda = ldb = F_; ldc = 8192; KD = F_; }
    if constexpr (MODE == 4) {
        Ap = g_Q + (size_t)zb * N_ * F_ + zh * HD_; lda = F_;
        Bp = g_K + (size_t)zb * N_ * F_ + zh * HD_; ldb = F_;
        Cp = g_A + (size_t)(blockIdx.z) * N_ * N_;  ldc = N_; KD = HD_;
    }
    if constexpr (MODE == 5) {
        Ap = g_A + (size_t)(blockIdx.z) * N_ * N_;          lda = N_;
        Bp = g_VpT + (size_t)zh * HD_ * 8192 + zb * N_;     ldb = 8192;
        Cp = outp + (size_t)zb * N_ * F_ + zh * HD_;        ldc = F_; KD = F_;
    }

    float acc[4][8][4];
    #pragma unroll
    for (int i = 0; i < 4; i++)
        #pragma unroll
        for (int j = 0; j < 8; j++)
            #pragma unroll
            for (int k = 0; k < 4; k++) acc[i][j][k] = 0.f;

    // ---- cp.async geometry: thread covers chunk (tid&7), rows (tid>>3)+16i ----
    const int ldRow0 = tid >> 3;
    const int ldCh   = tid & 7;
    const uint32_t ldSwz = (uint32_t)((ldCh ^ (ldRow0 & 7)) << 4);

    auto loadTile = [&](int kt, int s) {
        const int k0 = kt * BK;
        const uint32_t aS = smemU + (uint32_t)(s * STAGE_BYTES);
        const uint32_t bS = smemU + (uint32_t)(2 * STAGE_BYTES + s * STAGE_BYTES);
        #pragma unroll
        for (int i = 0; i < 8; i++) {
            const int row = ldRow0 + 16 * i;
            cp16s(aS + (uint32_t)row * 128u + ldSwz,
                  Ap + (size_t)(ro + row) * lda + k0 + ldCh * 4);
            cp16s(bS + (uint32_t)row * 128u + ldSwz,
                  Bp + (size_t)(co + row) * ldb + k0 + ldCh * 4);
        }
    };

    // ---- ldmatrix geometry ----
    const int aRowT = lane & 15;             // tile row offset within 16
    const int aSel  = lane >> 4;             // 0: k-chunk c0, 1: c0+1
    const int aXr   = aRowT & 7;
    const int bRowT = (lane & 7) + ((lane >> 4) << 3);
    const int bSel  = (lane >> 3) & 1;
    const int bXr   = bRowT & 7;
    uint32_t aRowOff[4], bRowOff[4];
    #pragma unroll
    for (int mt = 0; mt < 4; mt++) aRowOff[mt] = (uint32_t)((wm0 + mt * 16 + aRowT) * 128);
    #pragma unroll
    for (int p = 0; p < 4; p++)   bRowOff[p]  = (uint32_t)((wn0 + p * 16 + bRowT) * 128);

    const int T = KD / BK;
    loadTile(0, 0);
    asm volatile("cp.async.commit_group;\n");

    for (int kt = 0; kt < T; ++kt) {
        const int s = kt & 1;
        if (kt + 1 < T) {
            loadTile(kt + 1, s ^ 1);
            asm volatile("cp.async.commit_group;\n");
            asm volatile("cp.async.wait_group 1;\n");
        } else {
            asm volatile("cp.async.wait_group 0;\n");
        }
        __syncthreads();

        const uint32_t aS = smemU + (uint32_t)(s * STAGE_BYTES);
        const uint32_t bS = smemU + (uint32_t)(2 * STAGE_BYTES + s * STAGE_BYTES);

        #pragma unroll
        for (int kk4 = 0; kk4 < 4; ++kk4) {          // k8 steps within k32
            const int c0 = kk4 * 2;
            uint32_t a[4][4], b[8][2];
            const uint32_t aCh = (uint32_t)(((c0 + aSel) ^ aXr) << 4);
            #pragma unroll
            for (int mt = 0; mt < 4; mt++)
                ldsm4(a[mt][0], a[mt][1], a[mt][2], a[mt][3], aS + aRowOff[mt] + aCh);
            const uint32_t bCh = (uint32_t)(((c0 + bSel) ^ bXr) << 4);
            #pragma unroll
            for (int p = 0; p < 4; p++)
                ldsm4(b[2*p][0], b[2*p][1], b[2*p+1][0], b[2*p+1][1], bS + bRowOff[p] + bCh);
            #pragma unroll
            for (int mt = 0; mt < 4; mt++)
                #pragma unroll
                for (int nt = 0; nt < 8; nt++) mma_tf32(acc[mt][nt], a[mt], b[nt]);
        }
        __syncthreads();
    }

    // ------------------------------ epilogues -------------------------------
    if constexpr (MODE == 3) {
        #pragma unroll
        for (int half = 0; half < 2; ++half) {
            __syncthreads();
            #pragma unroll
            for (int mt = 0; mt < 4; mt++)
                #pragma unroll
                for (int nt = 0; nt < 8; nt++)
                    #pragma unroll
                    for (int h2 = 0; h2 < 2; h2++)
                        #pragma unroll
                        for (int j = 0; j < 2; j++) {
                            const int colL = wn0 + nt * 8 + c * 2 + j;
                            if ((colL >> 6) == half) {
                                const int rowL = wm0 + mt * 16 + r + h2 * 8;
                                smf[(colL & 63) * 132 + rowL] =
                                    rna(acc[mt][nt][h2 * 2 + j] + g_bvp[co + colL]);
                            }
                        }
            __syncthreads();
            #pragma unroll
            for (int i = 0; i < 16; i++) {
                const int q = tid + 128 * i;            // 0..2047
                const int fr = q >> 5, m4 = q & 31;
                float4 v = *(const float4*)&smf[fr * 132 + m4 * 4];
                *(float4*)&g_VpT[(size_t)(co + half * 64 + fr) * 8192 + ro + m4 * 4] = v;
            }
        }
        return;
    }

    const int* adjr = nullptr; const float* labr = nullptr;
    if constexpr (MODE == 4) {
        adjr = adj   + (size_t)zb * N_ * N_;
        labr = label + (size_t)zb * N_ * N_;
    }

    #pragma unroll
    for (int mt = 0; mt < 4; mt++)
        #pragma unroll
        for (int nt = 0; nt < 8; nt++)
            #pragma unroll
            for (int h2 = 0; h2 < 2; h2++) {
                const int row  = ro + wm0 + mt * 16 + r + h2 * 8;
                const int colL = wn0 + nt * 8 + c * 2;
                const int col  = co + colL;
                float v0 = acc[mt][nt][h2 * 2 + 0];
                float v1 = acc[mt][nt][h2 * 2 + 1];
                if constexpr (MODE == 0) { v0 = rna(v0); v1 = rna(v1); }
                if constexpr (MODE == 1 || MODE == 2) {
                    v0 = rna(v0 + bias[col]); v1 = rna(v1 + bias[col + 1]);
                }
                if constexpr (MODE == 4) {
                    const int2   av = *(const int2*)  &adjr[(size_t)row * N_ + col];
                    const float2 lv = *(const float2*)&labr[(size_t)row * N_ + col];
                    v0 = (av.x > 0 ? v0 * SCALE_ : NEGINF_) + lv.x;
                    v1 = (av.y > 0 ? v1 * SCALE_ : NEGINF_) + lv.y;
                }
                if constexpr (MODE == 5) {
                    v0 += bias[colL]; v1 += bias[colL + 1];   // bias = bo + h*HD
                }
                *(float2*)&Cp[(size_t)row * ldc + col] = make_float2(v0, v1);
            }
}

// --------------- fused softmax (all heads of one (b,n) row) + att_avg -------
__global__ void softmax_attavg_kernel(float* __restrict__ out_att) {
    const int b = blockIdx.x >> 10, n = blockIdx.x & 1023;
    const int t = threadIdx.x;
    __shared__ float redm[8], reds[8];

    float4 avg = make_float4(0.f, 0.f, 0.f, 0.f);
    #pragma unroll
    for (int h = 0; h < H_; h++) {
        float* p = g_A + (((size_t)(b * H_ + h) * N_ + n) * N_) + t * 4;
        float4 v = *(float4*)p;

        float mx = fmaxf(fmaxf(v.x, v.y), fmaxf(v.z, v.w));
        #pragma unroll
        for (int o = 16; o; o >>= 1) mx = fmaxf(mx, __shfl_xor_sync(0xffffffffu, mx, o));
        __syncthreads();
        if ((t & 31) == 0) redm[t >> 5] = mx;
        __syncthreads();
        mx = redm[0];
        #pragma unroll
        for (int w = 1; w < 8; w++) mx = fmaxf(mx, redm[w]);

        float4 e;
        e.x = __expf(v.x - mx); e.y = __expf(v.y - mx);
        e.z = __expf(v.z - mx); e.w = __expf(v.w - mx);
        float s = e.x + e.y + e.z + e.w;
        #pragma unroll
        for (int o = 16; o; o >>= 1) s += __shfl_xor_sync(0xffffffffu, s, o);
        __syncthreads();
        if ((t & 31) == 0) reds[t >> 5] = s;
        __syncthreads();
        s = reds[0];
        #pragma unroll
        for (int w = 1; w < 8; w++) s += reds[w];

        const float inv = 1.0f / s;
        e.x *= inv; e.y *= inv; e.z *= inv; e.w *= inv;
        avg.x += e.x; avg.y += e.y; avg.z += e.z; avg.w += e.w;
        float4 o4 = make_float4(rna(e.x), rna(e.y), rna(e.z), rna(e.w));
        *(float4*)p = o4;
    }
    avg.x *= 0.125f; avg.y *= 0.125f; avg.z *= 0.125f; avg.w *= 0.125f;
    *(float4*)(out_att + ((size_t)b * N_ + n) * N_ + t * 4) = avg;
}

// ----------------------------------------------------------------------------
extern "C" void kernel_launch(void* const* d_in, const int* in_sizes, int n_in,
                              void* d_out, int out_size) {
    const float* obj   = (const float*)d_in[0];
    const float* cross = (const float*)d_in[1];
    const int*   adj   = (const int*)  d_in[2];
    const float* label = (const float*)d_in[3];
    const float* Wq    = (const float*)d_in[4];
    const float* bq    = (const float*)d_in[5];
    const float* Wk    = (const float*)d_in[6];
    const float* bk    = (const float*)d_in[7];
    const float* Wv    = (const float*)d_in[8];
    const float* bv    = (const float*)d_in[9];
    const float* Wo    = (const float*)d_in[10];
    const float* bo    = (const float*)d_in[11];

    float* out     = (float*)d_out;
    float* out_att = out + (size_t)B_ * N_ * F_;

    float *objR, *crossR, *WqR, *WkR, *WoR, *WvT;
    cudaGetSymbolAddress((void**)&objR,   g_objR);
    cudaGetSymbolAddress((void**)&crossR, g_crossR);
    cudaGetSymbolAddress((void**)&WqR,    g_WqR);
    cudaGetSymbolAddress((void**)&WkR,    g_WkR);
    cudaGetSymbolAddress((void**)&WoR,    g_WoR);
    cudaGetSymbolAddress((void**)&WvT,    g_WvT);

    // allow 64 KB dynamic smem on the GEMM instantiations (host-side, idempotent)
    cudaFuncSetAttribute(tgemm<0>, cudaFuncAttributeMaxDynamicSharedMemorySize, SMEM_BYTES);
    cudaFuncSetAttribute(tgemm<1>, cudaFuncAttributeMaxDynamicSharedMemorySize, SMEM_BYTES);
    cudaFuncSetAttribute(tgemm<2>, cudaFuncAttributeMaxDynamicSharedMemorySize, SMEM_BYTES);
    cudaFuncSetAttribute(tgemm<3>, cudaFuncAttributeMaxDynamicSharedMemorySize, SMEM_BYTES);
    cudaFuncSetAttribute(tgemm<4>, cudaFuncAttributeMaxDynamicSharedMemorySize, SMEM_BYTES);
    cudaFuncSetAttribute(tgemm<5>, cudaFuncAttributeMaxDynamicSharedMemorySize, SMEM_BYTES);

    // round external GEMM inputs to tf32 (RNA)
    round_pass<<<8192, 256>>>(obj,   objR);
    round_pass<<<8192, 256>>>(cross, crossR);
    round_pass<<<1024, 256>>>(Wq, WqR);
    round_pass<<<1024, 256>>>(Wk, WkR);
    round_pass<<<1024, 256>>>(Wo, WoR);
    transpose_round_kernel<<<dim3(32, 32), dim3(32, 8)>>>(Wv, WvT);
    fold_bias_kernel<<<F_, 256>>>(Wo, bv);

    // GEMMs
    tgemm<0><<<dim3(8, 8),     128, SMEM_BYTES>>>(nullptr, nullptr, nullptr, nullptr); // fold
    tgemm<1><<<dim3(8, 64),    128, SMEM_BYTES>>>(bq,      nullptr, nullptr, nullptr); // Q
    tgemm<2><<<dim3(8, 64),    128, SMEM_BYTES>>>(bk,      nullptr, nullptr, nullptr); // K
    tgemm<3><<<dim3(8, 64),    128, SMEM_BYTES>>>(nullptr, nullptr, nullptr, nullptr); // VpT
    tgemm<4><<<dim3(8, 8, 64), 128, SMEM_BYTES>>>(nullptr, adj,     label,   nullptr); // scores
    softmax_attavg_kernel<<<B_ * N_, 256>>>(out_att);
    tgemm<5><<<dim3(1, 8, 64), 128, SMEM_BYTES>>>(bo,      nullptr, nullptr, out);     // AV
}